// round 3
// baseline (speedup 1.0000x reference)
#include <cuda_runtime.h>

#define NN 50000
#define EE 800000
#define HH 4

// ---------------- scratch (static __device__, no allocations) ----------------
__device__ __align__(16) float g_xl[NN * 256];      // xl1 [N,256] then xl2 [N,128]
__device__ __align__(16) float g_out1[NN * 64];     // layer-1 output [N,64]
__device__ __align__(16) float g_P[NN * 128];       // node projections for edge MLP
__device__ __align__(16) float g_alpha[EE * 4];     // raw leaky-relu attention logits
__device__ __align__(16) float g_alphan[EE * 4];    // normalized alpha (layer 2)
__device__ __align__(16) float g_asrc[NN * 4];
__device__ __align__(16) float g_adst[NN * 4];
__device__ __align__(16) float g_nodeM[NN * 4];     // per-node softmax max (layer 2)
__device__ __align__(16) float g_nodeR[NN * 4];     // per-node 1/(sum+eps)  (layer 2)
__device__ int g_deg[NN];
__device__ int g_cursor[NN];
__device__ int g_rowptr[NN + 1];
__device__ int g_perm[EE];            // edge ids sorted by dst
__device__ int g_srcs[EE];            // src node per sorted edge

// ---------------- CSR build ----------------
__global__ void zero_counts_kernel() {
    int i = blockIdx.x * blockDim.x + threadIdx.x;
    if (i < NN) { g_deg[i] = 0; g_cursor[i] = 0; }
}

__global__ void hist_kernel(const int* __restrict__ ei) {
    int e = blockIdx.x * blockDim.x + threadIdx.x;
    if (e >= EE) return;
    atomicAdd(&g_deg[ei[EE + e]], 1);
}

__global__ void scan_kernel() {
    __shared__ int sh[1024];
    int t = threadIdx.x;
    const int chunk = (NN + 1023) / 1024;
    int beg = t * chunk;
    int end = beg + chunk; if (end > NN) end = NN; if (beg > NN) beg = NN;
    int s = 0;
    for (int i = beg; i < end; i++) s += g_deg[i];
    sh[t] = s;
    __syncthreads();
    for (int off = 1; off < 1024; off <<= 1) {
        int v = (t >= off) ? sh[t - off] : 0;
        __syncthreads();
        sh[t] += v;
        __syncthreads();
    }
    int run = (t > 0) ? sh[t - 1] : 0;
    for (int i = beg; i < end; i++) { g_rowptr[i] = run; run += g_deg[i]; }
    if (t == 0) g_rowptr[NN] = sh[1023];
}

__global__ void scatter_kernel(const int* __restrict__ ei) {
    int e = blockIdx.x * blockDim.x + threadIdx.x;
    if (e >= EE) return;
    int d = ei[EE + e];
    int pos = g_rowptr[d] + atomicAdd(&g_cursor[d], 1);
    g_perm[pos] = e;
    g_srcs[pos] = ei[e];
}

// ---------------- SGEMM: C[MxNd] = A[MxK] @ B[KxNd], row-major ----------------
#define BM 64
#define BN 64
#define BK 16
__global__ __launch_bounds__(256) void sgemm_kernel(
    const float* __restrict__ A, const float* __restrict__ B,
    float* __restrict__ C, int M, int K, int Nd) {
    __shared__ float As[BK][BM];
    __shared__ float Bs[BK][BN];
    int tid = threadIdx.x;
    int block_m = blockIdx.y * BM;
    int block_n = blockIdx.x * BN;
    int tr = tid >> 4, tc = tid & 15;
    float acc[4][4] = {};
    for (int k0 = 0; k0 < K; k0 += BK) {
#pragma unroll
        for (int i = 0; i < (BM * BK) / 256; i++) {
            int idx = tid + i * 256;
            int m = idx / BK, kk = idx % BK;
            int row = block_m + m;
            As[kk][m] = (row < M) ? A[(size_t)row * K + k0 + kk] : 0.f;
        }
#pragma unroll
        for (int i = 0; i < (BK * BN) / 256; i++) {
            int idx = tid + i * 256;
            int kk = idx / BN, nn = idx % BN;
            Bs[kk][nn] = B[(size_t)(k0 + kk) * Nd + block_n + nn];
        }
        __syncthreads();
#pragma unroll
        for (int kk = 0; kk < BK; kk++) {
            float4 a4 = *(const float4*)&As[kk][tr * 4];
            float4 b4 = *(const float4*)&Bs[kk][tc * 4];
            float av[4] = {a4.x, a4.y, a4.z, a4.w};
            float bv[4] = {b4.x, b4.y, b4.z, b4.w};
#pragma unroll
            for (int i = 0; i < 4; i++)
#pragma unroll
                for (int j = 0; j < 4; j++) acc[i][j] += av[i] * bv[j];
        }
        __syncthreads();
    }
#pragma unroll
    for (int i = 0; i < 4; i++) {
        int row = block_m + tr * 4 + i;
        if (row < M) {
            float4 v = make_float4(acc[i][0], acc[i][1], acc[i][2], acc[i][3]);
            *(float4*)&C[(size_t)row * Nd + block_n + tc * 4] = v;
        }
    }
}

// ---------------- attention dot products: warp per node ----------------
template <int C>
__global__ void att_dot_kernel(const float* __restrict__ xl,
                               const float* __restrict__ att_src,
                               const float* __restrict__ att_dst) {
    const int CH = HH * C;
    const int V = CH / 32;
    int warp = (blockIdx.x * blockDim.x + threadIdx.x) >> 5;
    int lane = threadIdx.x & 31;
    if (warp >= NN) return;
    const float* xr = xl + (size_t)warp * CH + lane * V;
    int h = (lane * V) / C;
    int cbase = (lane * V) % C;
    float ps = 0.f, pd = 0.f;
#pragma unroll
    for (int j = 0; j < V; j++) {
        float v = xr[j];
        ps += v * att_src[h * C + cbase + j];
        pd += v * att_dst[h * C + cbase + j];
    }
#pragma unroll
    for (int off = 4; off; off >>= 1) {
        ps += __shfl_xor_sync(0xffffffff, ps, off);
        pd += __shfl_xor_sync(0xffffffff, pd, off);
    }
    if ((lane & 7) == 0) {
        g_asrc[warp * 4 + (lane >> 3)] = ps;
        g_adst[warp * 4 + (lane >> 3)] = pd;
    }
}

// ---------------- per-edge raw attention logits ----------------
__device__ __forceinline__ float lrelu(float v) { return v > 0.f ? v : 0.2f * v; }

__global__ void edge_alpha_kernel(const int* __restrict__ ei) {
    int e = blockIdx.x * blockDim.x + threadIdx.x;
    if (e >= EE) return;
    int s = ei[e];
    int d = ei[EE + e];
    float4 as = *(const float4*)&g_asrc[s * 4];
    float4 ad = *(const float4*)&g_adst[d * 4];
    float4 al;
    al.x = lrelu(as.x + ad.x);
    al.y = lrelu(as.y + ad.y);
    al.z = lrelu(as.z + ad.z);
    al.w = lrelu(as.w + ad.w);
    *(float4*)&g_alpha[e * 4] = al;
}

// ---------------- softmax + aggregate + head-mean + bias: warp per node ----------------
template <int C, bool WRITE_STATS>
__global__ void aggregate_kernel(const float* __restrict__ xl,
                                 const float* __restrict__ bias,
                                 float* __restrict__ out) {
    const int CH = HH * C;
    const int V = CH / 32;
    int warp = (blockIdx.x * blockDim.x + threadIdx.x) >> 5;
    int lane = threadIdx.x & 31;
    if (warp >= NN) return;
    int start = g_rowptr[warp], end = g_rowptr[warp + 1];

    float m[4] = {-1e30f, -1e30f, -1e30f, -1e30f};
    for (int i = start + lane; i < end; i += 32) {
        int e = g_perm[i];
        float4 a = *(const float4*)&g_alpha[e * 4];
        m[0] = fmaxf(m[0], a.x); m[1] = fmaxf(m[1], a.y);
        m[2] = fmaxf(m[2], a.z); m[3] = fmaxf(m[3], a.w);
    }
#pragma unroll
    for (int off = 16; off; off >>= 1)
#pragma unroll
        for (int h = 0; h < 4; h++)
            m[h] = fmaxf(m[h], __shfl_xor_sync(0xffffffff, m[h], off));

    float s[4] = {0.f, 0.f, 0.f, 0.f};
    for (int i = start + lane; i < end; i += 32) {
        int e = g_perm[i];
        float4 a = *(const float4*)&g_alpha[e * 4];
        s[0] += __expf(a.x - m[0]); s[1] += __expf(a.y - m[1]);
        s[2] += __expf(a.z - m[2]); s[3] += __expf(a.w - m[3]);
    }
#pragma unroll
    for (int off = 16; off; off >>= 1)
#pragma unroll
        for (int h = 0; h < 4; h++)
            s[h] += __shfl_xor_sync(0xffffffff, s[h], off);

    if (WRITE_STATS && lane < 4) {
        g_nodeM[warp * 4 + lane] = m[lane];
        g_nodeR[warp * 4 + lane] = 1.f / (s[lane] + 1e-16f);
    }

    int myh = lane >> 3;
    float myM = m[myh];
    float myR = 1.f / (s[myh] + 1e-16f);

    float acc[V];
#pragma unroll
    for (int j = 0; j < V; j++) acc[j] = 0.f;

    for (int i = start; i < end; i++) {
        int e = g_perm[i];
        int sn = g_srcs[i];
        float al = __expf(g_alpha[e * 4 + myh] - myM) * myR;
        const float4* x4 = (const float4*)(xl + (size_t)sn * CH + lane * V);
#pragma unroll
        for (int j4 = 0; j4 < V / 4; j4++) {
            float4 v = x4[j4];
            acc[j4 * 4 + 0] += al * v.x;
            acc[j4 * 4 + 1] += al * v.y;
            acc[j4 * 4 + 2] += al * v.z;
            acc[j4 * 4 + 3] += al * v.w;
        }
    }
#pragma unroll
    for (int j = 0; j < V; j++) {
        acc[j] += __shfl_xor_sync(0xffffffff, acc[j], 8);
        acc[j] += __shfl_xor_sync(0xffffffff, acc[j], 16);
    }
    if (lane < 8) {
#pragma unroll
        for (int j = 0; j < V; j++)
            out[(size_t)warp * C + lane * V + j] = acc[j] * 0.25f + bias[lane * V + j];
    }
}

// ---------------- normalized alpha per edge (direct transcription of reference) ----------------
__global__ void edge_alphan_kernel(const int* __restrict__ ei) {
    int e = blockIdx.x * blockDim.x + threadIdx.x;
    if (e >= EE) return;
    int d = ei[EE + e];
    float4 a = *(const float4*)&g_alpha[e * 4];
    float4 M = *(const float4*)&g_nodeM[d * 4];
    float4 R = *(const float4*)&g_nodeR[d * 4];
    float4 o;
    o.x = __expf(a.x - M.x) * R.x;
    o.y = __expf(a.y - M.y) * R.y;
    o.z = __expf(a.z - M.z) * R.z;
    o.w = __expf(a.w - M.w) * R.w;
    *(float4*)&g_alphan[e * 4] = o;
}

// ---------------- node projections P[n] = out2[n] @ [mW1_src | mW1_dst] ----------------
__global__ __launch_bounds__(256) void build_P_kernel(const float* __restrict__ out2,
                                                      const float* __restrict__ mW1) {
    __shared__ float sWp[32 * 128];
    int tid = threadIdx.x;
    for (int idx = tid; idx < 32 * 128; idx += 256) {
        int k = idx >> 7, j = idx & 127;
        sWp[idx] = (j < 64) ? mW1[k * 64 + j] : mW1[(36 + k) * 64 + (j - 64)];
    }
    __syncthreads();
    int node = (blockIdx.x * 256 + tid) >> 5;
    int lane = tid & 31;
    if (node >= NN) return;
    float own = out2[(size_t)node * 32 + lane];
    float a0 = 0.f, a1 = 0.f, a2 = 0.f, a3 = 0.f;
#pragma unroll
    for (int k = 0; k < 32; k++) {
        float f = __shfl_sync(0xffffffff, own, k);
        a0 += f * sWp[k * 128 + lane];
        a1 += f * sWp[k * 128 + lane + 32];
        a2 += f * sWp[k * 128 + lane + 64];
        a3 += f * sWp[k * 128 + lane + 96];
    }
    float* Pr = &g_P[(size_t)node * 128];
    Pr[lane]      = a0;
    Pr[lane + 32] = a1;
    Pr[lane + 64] = a2;
    Pr[lane + 96] = a3;
}

// ---------------- edge MLP finish: warp per edge ----------------
__global__ __launch_bounds__(256) void edge_mlp_kernel(
    const int* __restrict__ ei,
    const float* __restrict__ mW1, const float* __restrict__ mb1,
    const float* __restrict__ mW2, const float* __restrict__ mb2,
    float* __restrict__ edge_out) {
    __shared__ float sWa[4 * 64];   // mW1 rows 32..35 (alpha rows)
    __shared__ float sW2[128];      // mW2 [64,2]
    __shared__ float sb1[64];
    int tid = threadIdx.x;
    sWa[tid] = mW1[(32 + (tid >> 6)) * 64 + (tid & 63)];
    if (tid < 128) sW2[tid] = mW2[tid];
    if (tid < 64)  sb1[tid] = mb1[tid];
    __syncthreads();

    int e = (blockIdx.x * 256 + tid) >> 5;
    int lane = tid & 31;
    if (e >= EE) return;
    int s = ei[e], d = ei[EE + e];
    float4 a = *(const float4*)&g_alphan[e * 4];
    const float* Ps = &g_P[(size_t)s * 128];
    const float* Pd = &g_P[(size_t)d * 128 + 64];
    int c0 = lane, c1 = lane + 32;

    float h0 = Ps[c0] + Pd[c0] + sb1[c0]
             + a.x * sWa[c0] + a.y * sWa[64 + c0] + a.z * sWa[128 + c0] + a.w * sWa[192 + c0];
    float h1 = Ps[c1] + Pd[c1] + sb1[c1]
             + a.x * sWa[c1] + a.y * sWa[64 + c1] + a.z * sWa[128 + c1] + a.w * sWa[192 + c1];
    h0 = fmaxf(h0, 0.f);
    h1 = fmaxf(h1, 0.f);
    float s0 = h0 * sW2[c0 * 2 + 0] + h1 * sW2[c1 * 2 + 0];
    float s1 = h0 * sW2[c0 * 2 + 1] + h1 * sW2[c1 * 2 + 1];
#pragma unroll
    for (int off = 16; off; off >>= 1) {
        s0 += __shfl_xor_sync(0xffffffff, s0, off);
        s1 += __shfl_xor_sync(0xffffffff, s1, off);
    }
    if (lane == 0) {
        edge_out[(size_t)e * 2 + 0] = s0 + mb2[0];
        edge_out[(size_t)e * 2 + 1] = s1 + mb2[1];
    }
}

// ---------------- launch ----------------
extern "C" void kernel_launch(void* const* d_in, const int* in_sizes, int n_in,
                              void* d_out, int out_size) {
    const float* x        = (const float*)d_in[0];
    const int*   ei       = (const int*)d_in[1];
    const float* W1       = (const float*)d_in[4];
    const float* att1_src = (const float*)d_in[5];
    const float* att1_dst = (const float*)d_in[6];
    const float* b1       = (const float*)d_in[7];
    const float* W3       = (const float*)d_in[8];
    const float* att3_src = (const float*)d_in[9];
    const float* att3_dst = (const float*)d_in[10];
    const float* b3       = (const float*)d_in[11];
    const float* mW1      = (const float*)d_in[12];
    const float* mb1      = (const float*)d_in[13];
    const float* mW2      = (const float*)d_in[14];
    const float* mb2      = (const float*)d_in[15];

    float* out2     = (float*)d_out;          // [N, 32]
    float* edge_out = out2 + (size_t)NN * 32; // [E, 2]

    // CSR by destination
    zero_counts_kernel<<<(NN + 255) / 256, 256>>>();
    hist_kernel<<<(EE + 255) / 256, 256>>>(ei);
    scan_kernel<<<1, 1024>>>();
    scatter_kernel<<<(EE + 255) / 256, 256>>>(ei);

    // Layer 1
    {
        dim3 grid(256 / BN, (NN + BM - 1) / BM);
        sgemm_kernel<<<grid, 256>>>(x, W1, g_xl, NN, 128, 256);
    }
    att_dot_kernel<64><<<(NN * 32 + 255) / 256, 256>>>(g_xl, att1_src, att1_dst);
    edge_alpha_kernel<<<(EE + 255) / 256, 256>>>(ei);
    aggregate_kernel<64, false><<<(NN * 32 + 255) / 256, 256>>>(g_xl, b1, g_out1);

    // Layer 2
    {
        dim3 grid(128 / BN, (NN + BM - 1) / BM);
        sgemm_kernel<<<grid, 256>>>(g_out1, W3, g_xl, NN, 64, 128);
    }
    att_dot_kernel<32><<<(NN * 32 + 255) / 256, 256>>>(g_xl, att3_src, att3_dst);
    edge_alpha_kernel<<<(EE + 255) / 256, 256>>>(ei);
    aggregate_kernel<32, true><<<(NN * 32 + 255) / 256, 256>>>(g_xl, b3, out2);

    // Edge outputs
    edge_alphan_kernel<<<(EE + 255) / 256, 256>>>(ei);
    build_P_kernel<<<(NN * 32 + 255) / 256, 256>>>(out2, mW1);
    edge_mlp_kernel<<<(EE * 32 + 255) / 256, 256>>>(ei, mW1, mb1, mW2, mb2, edge_out);
}